// round 1
// baseline (speedup 1.0000x reference)
#include <cuda_runtime.h>
#include <math.h>

// Problem constants
#define BTN   128          // B*T
#define SEQ   256
#define DIM   1024
#define NH    16
#define NKV   4
#define HD    64
#define GRP   4            // NH / NKV
#define MROWS (BTN*SEQ)    // 32768
#define QKVC  1536         // 1024 Q + 256 K + 256 V
#define EPSV  1e-6f
#define SCALEV 0.125f      // HD^-0.5
#define CAPV  50.0f

// Scratch (device globals — no allocations allowed)
__device__ float g_qkv[(size_t)MROWS * QKVC];   // (m, [Q(1024) K(256) V(256)])
__device__ float g_attn[(size_t)MROWS * DIM];   // (m, h*64+hd)

// ---------------------------------------------------------------------------
// Tiled fp32 GEMM: C[m, n] = sum_k A[m,k] * W[k,n]
// BM=BN=128, BK=16, 256 threads, 8x8 per-thread micro-tile.
// M is implied by gridDim.y*128. All dims assumed multiples of tile sizes.
// ---------------------------------------------------------------------------
#define BM 128
#define BN 128
#define BK 16

__global__ void __launch_bounds__(256)
gemm128(const float* __restrict__ A, const float* __restrict__ W,
        float* __restrict__ C, int N, int K, int ldc)
{
    __shared__ float As[BK][BM];
    __shared__ float Bs[BK][BN];

    const int bn = blockIdx.x * BN;
    const int bm = blockIdx.y * BM;
    const int tid = threadIdx.x;
    const int tx = tid & 15;        // 0..15 -> n
    const int ty = tid >> 4;        // 0..15 -> m

    // A-tile loader mapping: 128 rows x 16 cols = 512 float4, 2 per thread
    const int arow = tid >> 2;          // 0..63 (two passes: +0, +64)
    const int acol = (tid & 3) * 4;     // 0,4,8,12
    // B-tile loader mapping: 16 rows x 128 cols = 512 float4, 2 per thread
    const int brow = tid >> 5;          // 0..7 (two passes: +0, +8)
    const int bcol = (tid & 31) * 4;    // 0..124

    float acc[8][8];
    #pragma unroll
    for (int i = 0; i < 8; i++)
        #pragma unroll
        for (int j = 0; j < 8; j++) acc[i][j] = 0.f;

    for (int k0 = 0; k0 < K; k0 += BK) {
        // load A tile (transposed into As[k][m])
        #pragma unroll
        for (int r = 0; r < 2; r++) {
            int row = arow + r * 64;
            float4 v = *(const float4*)&A[(size_t)(bm + row) * K + k0 + acol];
            As[acol + 0][row] = v.x;
            As[acol + 1][row] = v.y;
            As[acol + 2][row] = v.z;
            As[acol + 3][row] = v.w;
        }
        // load B tile
        #pragma unroll
        for (int r = 0; r < 2; r++) {
            int row = brow + r * 8;
            *(float4*)&Bs[row][bcol] =
                *(const float4*)&W[(size_t)(k0 + row) * N + bn + bcol];
        }
        __syncthreads();

        #pragma unroll
        for (int kk = 0; kk < BK; kk++) {
            float a[8], b[8];
            *(float4*)&a[0] = *(const float4*)&As[kk][ty * 8 + 0];
            *(float4*)&a[4] = *(const float4*)&As[kk][ty * 8 + 4];
            *(float4*)&b[0] = *(const float4*)&Bs[kk][tx * 8 + 0];
            *(float4*)&b[4] = *(const float4*)&Bs[kk][tx * 8 + 4];
            #pragma unroll
            for (int i = 0; i < 8; i++)
                #pragma unroll
                for (int j = 0; j < 8; j++)
                    acc[i][j] = fmaf(a[i], b[j], acc[i][j]);
        }
        __syncthreads();
    }

    // store
    #pragma unroll
    for (int i = 0; i < 8; i++) {
        size_t rowoff = (size_t)(bm + ty * 8 + i) * ldc + bn + tx * 8;
        *(float4*)&C[rowoff + 0] = *(const float4*)&acc[i][0];
        *(float4*)&C[rowoff + 4] = *(const float4*)&acc[i][4];
    }
}

// ---------------------------------------------------------------------------
// Attention kernel: one block per (bt, h). 256 threads: one query per thread.
// K/V staged in SMEM (fp32). RMSNorms folded:
//   logit_j = (q * rq * wq * wk * SCALE) . k_raw_j * rmsinv_k_j
// soft cap + online softmax + PV accumulation in registers.
// ---------------------------------------------------------------------------
__global__ void __launch_bounds__(256, 1)
attn_kernel(const float* __restrict__ qw, const float* __restrict__ kw)
{
    extern __shared__ float smem[];
    float* sK  = smem;                  // [256][64]
    float* sV  = smem + SEQ * HD;       // [256][64]
    float* sRK = smem + 2 * SEQ * HD;   // [256] rms^-1 of K rows

    const int h  = blockIdx.x;
    const int bt = blockIdx.y;
    const int kvh = h / GRP;
    const int tid = threadIdx.x;

    const float* base = g_qkv + (size_t)bt * SEQ * QKVC;

    // cooperative K/V load: 4 threads per row (16 floats each)
    const int lane4 = tid & 3;
    const int rsub  = tid >> 2;     // 0..63
    for (int r = 0; r < 4; r++) {
        int j = r * 64 + rsub;
        const float* kp = base + (size_t)j * QKVC + DIM + kvh * HD + lane4 * 16;
        float ssq = 0.f;
        #pragma unroll
        for (int i = 0; i < 4; i++) {
            float4 v = *(const float4*)(kp + i * 4);
            ssq += v.x * v.x + v.y * v.y + v.z * v.z + v.w * v.w;
            *(float4*)&sK[j * HD + lane4 * 16 + i * 4] = v;
        }
        ssq += __shfl_xor_sync(0xffffffffu, ssq, 1);
        ssq += __shfl_xor_sync(0xffffffffu, ssq, 2);
        if (lane4 == 0) sRK[j] = rsqrtf(ssq * (1.0f / HD) + EPSV);

        const float* vp = base + (size_t)j * QKVC + DIM + NKV * HD + kvh * HD + lane4 * 16;
        #pragma unroll
        for (int i = 0; i < 4; i++)
            *(float4*)&sV[j * HD + lane4 * 16 + i * 4] = *(const float4*)(vp + i * 4);
    }
    __syncthreads();

    // per-thread query load + rmsnorm fold
    const int s = tid;
    const float* qp = base + (size_t)s * QKVC + h * HD;
    float q[HD];
    float ssq = 0.f;
    #pragma unroll
    for (int d = 0; d < HD; d += 4) {
        float4 v = *(const float4*)(qp + d);
        q[d] = v.x; q[d+1] = v.y; q[d+2] = v.z; q[d+3] = v.w;
        ssq += v.x * v.x + v.y * v.y + v.z * v.z + v.w * v.w;
    }
    const float rq = rsqrtf(ssq * (1.0f / HD) + EPSV);
    #pragma unroll
    for (int d = 0; d < HD; d++)
        q[d] *= rq * __ldg(&qw[d]) * __ldg(&kw[d]) * SCALEV;

    // flash loop
    float mx = -INFINITY, sum = 0.f;
    float acc[HD];
    #pragma unroll
    for (int d = 0; d < HD; d++) acc[d] = 0.f;

    for (int j = 0; j < SEQ; j++) {
        const float* kr = &sK[j * HD];
        float d0 = 0.f, d1 = 0.f, d2 = 0.f, d3 = 0.f;
        #pragma unroll
        for (int d = 0; d < HD; d += 4) {
            float4 kv = *(const float4*)(kr + d);
            d0 = fmaf(q[d],     kv.x, d0);
            d1 = fmaf(q[d + 1], kv.y, d1);
            d2 = fmaf(q[d + 2], kv.z, d2);
            d3 = fmaf(q[d + 3], kv.w, d3);
        }
        float l = (d0 + d1) + (d2 + d3);
        l *= sRK[j];
        l = CAPV * tanhf(l * (1.0f / CAPV));

        float mn = fmaxf(mx, l);
        float f  = __expf(mx - mn);   // first iter: exp(-inf) = 0
        float p  = __expf(l - mn);
        sum = sum * f + p;
        mx = mn;

        const float* vr = &sV[j * HD];
        #pragma unroll
        for (int d = 0; d < HD; d += 4) {
            float4 vv = *(const float4*)(vr + d);
            acc[d]     = fmaf(acc[d],     f, 0.f) + p * vv.x;
            acc[d + 1] = fmaf(acc[d + 1], f, 0.f) + p * vv.y;
            acc[d + 2] = fmaf(acc[d + 2], f, 0.f) + p * vv.z;
            acc[d + 3] = fmaf(acc[d + 3], f, 0.f) + p * vv.w;
        }
    }

    const float inv = 1.0f / sum;
    float* op = g_attn + (size_t)(bt * SEQ + s) * DIM + h * HD;
    #pragma unroll
    for (int d = 0; d < HD; d += 4) {
        float4 o;
        o.x = acc[d] * inv; o.y = acc[d+1] * inv;
        o.z = acc[d+2] * inv; o.w = acc[d+3] * inv;
        *(float4*)(op + d) = o;
    }
}

// ---------------------------------------------------------------------------
// launch
// ---------------------------------------------------------------------------
extern "C" void kernel_launch(void* const* d_in, const int* in_sizes, int n_in,
                              void* d_out, int out_size)
{
    const float* x  = (const float*)d_in[0];
    const float* Wq = (const float*)d_in[1];
    const float* Wk = (const float*)d_in[2];
    const float* Wv = (const float*)d_in[3];
    const float* Wo = (const float*)d_in[4];
    const float* qw = (const float*)d_in[5];
    const float* kw = (const float*)d_in[6];
    float* out = (float*)d_out;

    static float* qkv = nullptr;
    static float* att = nullptr;
    if (!qkv) {
        cudaGetSymbolAddress((void**)&qkv, g_qkv);
        cudaGetSymbolAddress((void**)&att, g_attn);
        cudaFuncSetAttribute(attn_kernel,
                             cudaFuncAttributeMaxDynamicSharedMemorySize,
                             (2 * SEQ * HD + SEQ) * (int)sizeof(float));
    }

    // QKV projections into one 1536-wide scratch
    gemm128<<<dim3(DIM / BN, MROWS / BM), 256>>>(x, Wq, qkv,            DIM, DIM, QKVC);
    gemm128<<<dim3(256 / BN, MROWS / BM), 256>>>(x, Wk, qkv + DIM,      256, DIM, QKVC);
    gemm128<<<dim3(256 / BN, MROWS / BM), 256>>>(x, Wv, qkv + DIM + 256, 256, DIM, QKVC);

    // attention
    attn_kernel<<<dim3(NH, BTN), 256,
                  (2 * SEQ * HD + SEQ) * sizeof(float)>>>(qw, kw);

    // output projection
    gemm128<<<dim3(DIM / BN, MROWS / BM), 256>>>(att, Wo, out, DIM, DIM, DIM);
}

// round 3
// speedup vs baseline: 1.8337x; 1.8337x over previous
#include <cuda_runtime.h>
#include <cuda_bf16.h>
#include <math.h>
#include <stdint.h>

// Problem constants
#define BTN   128
#define SEQ   256
#define DIM   1024
#define NH    16
#define NKV   4
#define HD    64
#define GRP   4
#define MROWS (BTN*SEQ)      // 32768
#define QKVC  1536
#define GK    1024
#define EPSV  1e-6f
#define SCALEV 0.125f
#define CAPV  50.0f

// ---------------------------------------------------------------------------
// Scratch (device globals)
// ---------------------------------------------------------------------------
__device__ float g_qkv[(size_t)MROWS * QKVC];
__device__ __align__(16) __nv_bfloat16 g_xh[(size_t)MROWS * GK];
__device__ __align__(16) __nv_bfloat16 g_xl[(size_t)MROWS * GK];
__device__ __align__(16) __nv_bfloat16 g_ah[(size_t)MROWS * GK];   // attn out hi
__device__ __align__(16) __nv_bfloat16 g_al[(size_t)MROWS * GK];   // attn out lo
__device__ __align__(16) __nv_bfloat16 g_wqkvh[(size_t)QKVC * GK]; // [n][k]
__device__ __align__(16) __nv_bfloat16 g_wqkvl[(size_t)QKVC * GK];
__device__ __align__(16) __nv_bfloat16 g_woh[(size_t)DIM * GK];
__device__ __align__(16) __nv_bfloat16 g_wol[(size_t)DIM * GK];

// ---------------------------------------------------------------------------
// helpers
// ---------------------------------------------------------------------------
__device__ __forceinline__ uint32_t smem_u32(const void* p) {
    uint32_t a;
    asm("{ .reg .u64 t; cvta.to.shared.u64 t, %1; cvt.u32.u64 %0, t; }"
        : "=r"(a) : "l"(p));
    return a;
}
__device__ __forceinline__ void cp16(uint32_t dst, const void* src) {
    asm volatile("cp.async.cg.shared.global [%0], [%1], 16;" :: "r"(dst), "l"(src));
}
__device__ __forceinline__ void ldmx4(uint32_t r[4], uint32_t addr) {
    asm volatile("ldmatrix.sync.aligned.m8n8.x4.shared.b16 {%0,%1,%2,%3}, [%4];"
                 : "=r"(r[0]), "=r"(r[1]), "=r"(r[2]), "=r"(r[3]) : "r"(addr));
}
__device__ __forceinline__ void ldmx2(uint32_t r[2], uint32_t addr) {
    asm volatile("ldmatrix.sync.aligned.m8n8.x2.shared.b16 {%0,%1}, [%2];"
                 : "=r"(r[0]), "=r"(r[1]) : "r"(addr));
}
__device__ __forceinline__ void mma16816(float c[4], const uint32_t a[4],
                                         const uint32_t b[2]) {
    asm volatile("mma.sync.aligned.m16n8k16.row.col.f32.bf16.bf16.f32 "
                 "{%0,%1,%2,%3}, {%4,%5,%6,%7}, {%8,%9}, {%0,%1,%2,%3};"
                 : "+f"(c[0]), "+f"(c[1]), "+f"(c[2]), "+f"(c[3])
                 : "r"(a[0]), "r"(a[1]), "r"(a[2]), "r"(a[3]),
                   "r"(b[0]), "r"(b[1]));
}

// ---------------------------------------------------------------------------
// conversions
// ---------------------------------------------------------------------------
__global__ void cvt_split(const float* __restrict__ in,
                          __nv_bfloat16* __restrict__ h,
                          __nv_bfloat16* __restrict__ l, int n4)
{
    int i = blockIdx.x * blockDim.x + threadIdx.x;
    if (i >= n4) return;
    float4 v = ((const float4*)in)[i];
    __nv_bfloat16 h0 = __float2bfloat16(v.x);
    __nv_bfloat16 h1 = __float2bfloat16(v.y);
    __nv_bfloat16 h2 = __float2bfloat16(v.z);
    __nv_bfloat16 h3 = __float2bfloat16(v.w);
    __nv_bfloat162* hp = (__nv_bfloat162*)h;
    __nv_bfloat162* lp = (__nv_bfloat162*)l;
    hp[2*i]   = __nv_bfloat162(h0, h1);
    hp[2*i+1] = __nv_bfloat162(h2, h3);
    lp[2*i]   = __nv_bfloat162(__float2bfloat16(v.x - __bfloat162float(h0)),
                               __float2bfloat16(v.y - __bfloat162float(h1)));
    lp[2*i+1] = __nv_bfloat162(__float2bfloat16(v.z - __bfloat162float(h2)),
                               __float2bfloat16(v.w - __bfloat162float(h3)));
}

__global__ void xpose_qkv(const float* __restrict__ Wq, const float* __restrict__ Wk,
                          const float* __restrict__ Wv,
                          __nv_bfloat16* __restrict__ th, __nv_bfloat16* __restrict__ tl)
{
    size_t idx = (size_t)blockIdx.x * blockDim.x + threadIdx.x;
    if (idx >= (size_t)QKVC * GK) return;
    int k = (int)(idx & (GK - 1));
    int n = (int)(idx >> 10);
    float v;
    if (n < DIM)            v = Wq[(size_t)k * (NH*HD)  + n];
    else if (n < DIM + 256) v = Wk[(size_t)k * (NKV*HD) + (n - DIM)];
    else                    v = Wv[(size_t)k * (NKV*HD) + (n - DIM - 256)];
    __nv_bfloat16 hv = __float2bfloat16(v);
    th[idx] = hv;
    tl[idx] = __float2bfloat16(v - __bfloat162float(hv));
}

__global__ void xpose_wo(const float* __restrict__ W,
                         __nv_bfloat16* __restrict__ th, __nv_bfloat16* __restrict__ tl)
{
    size_t idx = (size_t)blockIdx.x * blockDim.x + threadIdx.x;
    if (idx >= (size_t)DIM * GK) return;
    int k = (int)(idx & (GK - 1));
    int n = (int)(idx >> 10);
    float v = W[(size_t)k * DIM + n];
    __nv_bfloat16 hv = __float2bfloat16(v);
    th[idx] = hv;
    tl[idx] = __float2bfloat16(v - __bfloat162float(hv));
}

// ---------------------------------------------------------------------------
// HMMA bf16x3 GEMM: C[m,n] += A[m,:].B[n,:], A/B K-major bf16 hi/lo, K=1024.
// 128x128 CTA tile, BK=32, 3-stage cp.async, 8 warps (32x64 warp tiles).
// ---------------------------------------------------------------------------
#define BK      32
#define NCHUNK  (GK / BK)        // 32
#define ROWB    80               // padded row stride in bytes (40 bf16)
#define TILE_B  (128 * ROWB)     // 10240
#define STAGE_B (4 * TILE_B)     // Ah Al Bh Bl
#define NSTAGE  3
#define SMEM_GEMM (NSTAGE * STAGE_B)   // 122880

__device__ __forceinline__ void g_load(uint32_t sbase, int tid,
    const __nv_bfloat16* a_h, const __nv_bfloat16* a_l,
    const __nv_bfloat16* b_h, const __nv_bfloat16* b_l, int koff)
{
    #pragma unroll
    for (int it = 0; it < 2; it++) {
        int idx = tid + it * 256;
        int row = idx >> 2;
        int c4  = idx & 3;
        uint32_t dst = sbase + row * ROWB + c4 * 16;
        size_t so = (size_t)row * GK + koff + c4 * 8;
        cp16(dst + 0 * TILE_B, a_h + so);
        cp16(dst + 1 * TILE_B, a_l + so);
        cp16(dst + 2 * TILE_B, b_h + so);
        cp16(dst + 3 * TILE_B, b_l + so);
    }
    asm volatile("cp.async.commit_group;" ::: "memory");
}

__global__ void __launch_bounds__(256, 1)
gemm_mma(const __nv_bfloat16* __restrict__ ah, const __nv_bfloat16* __restrict__ al,
         const __nv_bfloat16* __restrict__ bh, const __nv_bfloat16* __restrict__ bl,
         float* __restrict__ C, int ldc)
{
    extern __shared__ char smem[];
    const uint32_t sb = smem_u32(smem);
    const int tid  = threadIdx.x;
    const int wid  = tid >> 5;
    const int lane = tid & 31;
    const int bm = blockIdx.y * 128;
    const int bn = blockIdx.x * 128;

    const __nv_bfloat16* Ah = ah + (size_t)bm * GK;
    const __nv_bfloat16* Al = al + (size_t)bm * GK;
    const __nv_bfloat16* Bh = bh + (size_t)bn * GK;
    const __nv_bfloat16* Bl = bl + (size_t)bn * GK;

    // warp tile: 32 (m) x 64 (n)
    const int wm = (wid & 3) * 32;
    const int wn = (wid >> 2) * 64;
    // ldmatrix lane addressing
    const int ar = lane & 15;                 // A row within 16
    const int ac = (lane >> 4) * 16;          // A k-half byte offset
    const int br = lane & 7;                  // B row within 8
    const int bc = ((lane >> 3) & 1) * 16;    // B k-half byte offset

    float acc[2][8][4];
    #pragma unroll
    for (int i = 0; i < 2; i++)
        #pragma unroll
        for (int j = 0; j < 8; j++)
            #pragma unroll
            for (int e = 0; e < 4; e++) acc[i][j][e] = 0.f;

    g_load(sb,           tid, Ah, Al, Bh, Bl, 0);
    g_load(sb + STAGE_B, tid, Ah, Al, Bh, Bl, BK);

    for (int c = 0; c < NCHUNK; c++) {
        if (c + 2 < NCHUNK) {
            g_load(sb + ((c + 2) % NSTAGE) * STAGE_B, tid, Ah, Al, Bh, Bl,
                   (c + 2) * BK);
            asm volatile("cp.async.wait_group 2;" ::: "memory");
        } else if (c + 1 < NCHUNK) {
            asm volatile("cp.async.wait_group 1;" ::: "memory");
        } else {
            asm volatile("cp.async.wait_group 0;" ::: "memory");
        }
        __syncthreads();

        const uint32_t st = sb + (c % NSTAGE) * STAGE_B;
        #pragma unroll
        for (int kk = 0; kk < 2; kk++) {
            const int kb = kk * 32;    // byte offset of k-16 half within 64B row
            uint32_t fAh[2][4], fAl[2][4];
            #pragma unroll
            for (int mt = 0; mt < 2; mt++) {
                uint32_t arow = (uint32_t)(wm + mt * 16 + ar) * ROWB + kb + ac;
                ldmx4(fAh[mt], st + 0 * TILE_B + arow);
                ldmx4(fAl[mt], st + 1 * TILE_B + arow);
            }
            uint32_t fBh[8][2], fBl[8][2];
            #pragma unroll
            for (int nt = 0; nt < 8; nt++) {
                uint32_t brow = (uint32_t)(wn + nt * 8 + br) * ROWB + kb + bc;
                ldmx2(fBh[nt], st + 2 * TILE_B + brow);
                ldmx2(fBl[nt], st + 3 * TILE_B + brow);
            }
            #pragma unroll
            for (int mt = 0; mt < 2; mt++)
                #pragma unroll
                for (int nt = 0; nt < 8; nt++) {
                    mma16816(acc[mt][nt], fAh[mt], fBh[nt]);
                    mma16816(acc[mt][nt], fAh[mt], fBl[nt]);
                    mma16816(acc[mt][nt], fAl[mt], fBh[nt]);
                }
        }
        __syncthreads();
    }

    // epilogue: c-frag thread t holds (r=t/4, c=2*(t%4)) and (+8, +1) pattern
    const int er = lane >> 2;
    const int ec = (lane & 3) * 2;
    #pragma unroll
    for (int mt = 0; mt < 2; mt++) {
        #pragma unroll
        for (int nt = 0; nt < 8; nt++) {
            size_t row0 = (size_t)(bm + wm + mt * 16 + er) * ldc
                        + bn + wn + nt * 8 + ec;
            *(float2*)&C[row0]            = make_float2(acc[mt][nt][0], acc[mt][nt][1]);
            *(float2*)&C[row0 + 8 * ldc]  = make_float2(acc[mt][nt][2], acc[mt][nt][3]);
        }
    }
}

// ---------------------------------------------------------------------------
// Attention: one block per (bt, h), 256 threads, one query each.
// Soft cap folded: p = exp(l - CAP) = exp(-2*CAP / (exp(2*z/CAP) + 1)).
// No online max / rescale needed (logits bounded by the cap).
// Writes attn output directly as bf16 hi/lo split.
// ---------------------------------------------------------------------------
__global__ void __launch_bounds__(256, 1)
attn_kernel(const float* __restrict__ qw, const float* __restrict__ kw)
{
    extern __shared__ float fsm[];
    float* sK  = fsm;
    float* sV  = fsm + SEQ * HD;
    float* sRK = fsm + 2 * SEQ * HD;

    const int h  = blockIdx.x;
    const int bt = blockIdx.y;
    const int kvh = h / GRP;
    const int tid = threadIdx.x;

    const float* base = g_qkv + (size_t)bt * SEQ * QKVC;

    const int lane4 = tid & 3;
    const int rsub  = tid >> 2;
    for (int r = 0; r < 4; r++) {
        int j = r * 64 + rsub;
        const float* kp = base + (size_t)j * QKVC + DIM + kvh * HD + lane4 * 16;
        float ssq = 0.f;
        #pragma unroll
        for (int i = 0; i < 4; i++) {
            float4 v = *(const float4*)(kp + i * 4);
            ssq += v.x * v.x + v.y * v.y + v.z * v.z + v.w * v.w;
            *(float4*)&sK[j * HD + lane4 * 16 + i * 4] = v;
        }
        ssq += __shfl_xor_sync(0xffffffffu, ssq, 1);
        ssq += __shfl_xor_sync(0xffffffffu, ssq, 2);
        if (lane4 == 0) sRK[j] = rsqrtf(ssq * (1.0f / HD) + EPSV);

        const float* vp = base + (size_t)j * QKVC + DIM + NKV * HD + kvh * HD + lane4 * 16;
        #pragma unroll
        for (int i = 0; i < 4; i++)
            *(float4*)&sV[j * HD + lane4 * 16 + i * 4] = *(const float4*)(vp + i * 4);
    }
    __syncthreads();

    const int s = tid;
    const float* qp = base + (size_t)s * QKVC + h * HD;
    float q[HD];
    float ssq = 0.f;
    #pragma unroll
    for (int d = 0; d < HD; d += 4) {
        float4 v = *(const float4*)(qp + d);
        q[d] = v.x; q[d+1] = v.y; q[d+2] = v.z; q[d+3] = v.w;
        ssq += v.x * v.x + v.y * v.y + v.z * v.z + v.w * v.w;
    }
    const float rq = rsqrtf(ssq * (1.0f / HD) + EPSV);
    // fold rmsnorm(q), weight vectors, attention scale AND 2/CAP into q
    const float qf = rq * SCALEV * (2.0f / CAPV);
    #pragma unroll
    for (int d = 0; d < HD; d++)
        q[d] *= qf * __ldg(&qw[d]) * __ldg(&kw[d]);

    float sum = 0.f;
    float acc[HD];
    #pragma unroll
    for (int d = 0; d < HD; d++) acc[d] = 0.f;

    for (int j = 0; j < SEQ; j++) {
        const float* kr = &sK[j * HD];
        float d0 = 0.f, d1 = 0.f, d2 = 0.f, d3 = 0.f;
        #pragma unroll
        for (int d = 0; d < HD; d += 4) {
            float4 kv = *(const float4*)(kr + d);
            d0 = fmaf(q[d],     kv.x, d0);
            d1 = fmaf(q[d + 1], kv.y, d1);
            d2 = fmaf(q[d + 2], kv.z, d2);
            d3 = fmaf(q[d + 3], kv.w, d3);
        }
        float z2c = ((d0 + d1) + (d2 + d3)) * sRK[j];   // 2*z/CAP
        float u = __expf(z2c);
        float p = __expf(__fdividef(-2.0f * CAPV, u + 1.0f));
        sum += p;

        const float* vr = &sV[j * HD];
        #pragma unroll
        for (int d = 0; d < HD; d += 4) {
            float4 vv = *(const float4*)(vr + d);
            acc[d]     = fmaf(p, vv.x, acc[d]);
            acc[d + 1] = fmaf(p, vv.y, acc[d + 1]);
            acc[d + 2] = fmaf(p, vv.z, acc[d + 2]);
            acc[d + 3] = fmaf(p, vv.w, acc[d + 3]);
        }
    }

    const float inv = 1.0f / sum;
    // write bf16 hi/lo split directly (input to the output-projection GEMM)
    size_t orow = (size_t)(bt * SEQ + s) * GK + h * HD;
    __nv_bfloat162* oh = (__nv_bfloat162*)(g_ah + orow);
    __nv_bfloat162* ol = (__nv_bfloat162*)(g_al + orow);
    #pragma unroll
    for (int d = 0; d < HD; d += 2) {
        float o0 = acc[d] * inv, o1 = acc[d + 1] * inv;
        __nv_bfloat16 h0 = __float2bfloat16(o0);
        __nv_bfloat16 h1 = __float2bfloat16(o1);
        oh[d >> 1] = __nv_bfloat162(h0, h1);
        ol[d >> 1] = __nv_bfloat162(__float2bfloat16(o0 - __bfloat162float(h0)),
                                    __float2bfloat16(o1 - __bfloat162float(h1)));
    }
}

// ---------------------------------------------------------------------------
// launch
// ---------------------------------------------------------------------------
extern "C" void kernel_launch(void* const* d_in, const int* in_sizes, int n_in,
                              void* d_out, int out_size)
{
    const float* x  = (const float*)d_in[0];
    const float* Wq = (const float*)d_in[1];
    const float* Wk = (const float*)d_in[2];
    const float* Wv = (const float*)d_in[3];
    const float* Wo = (const float*)d_in[4];
    const float* qw = (const float*)d_in[5];
    const float* kw = (const float*)d_in[6];
    float* out = (float*)d_out;

    static float* qkv = nullptr;
    static __nv_bfloat16 *xh, *xl, *aah, *aal, *wqh, *wql, *woh, *wol;
    if (!qkv) {
        cudaGetSymbolAddress((void**)&qkv, g_qkv);
        cudaGetSymbolAddress((void**)&xh,  g_xh);
        cudaGetSymbolAddress((void**)&xl,  g_xl);
        cudaGetSymbolAddress((void**)&aah, g_ah);
        cudaGetSymbolAddress((void**)&aal, g_al);
        cudaGetSymbolAddress((void**)&wqh, g_wqkvh);
        cudaGetSymbolAddress((void**)&wql, g_wqkvl);
        cudaGetSymbolAddress((void**)&woh, g_woh);
        cudaGetSymbolAddress((void**)&wol, g_wol);
        cudaFuncSetAttribute(attn_kernel,
                             cudaFuncAttributeMaxDynamicSharedMemorySize,
                             (2 * SEQ * HD + SEQ) * (int)sizeof(float));
        cudaFuncSetAttribute(gemm_mma,
                             cudaFuncAttributeMaxDynamicSharedMemorySize,
                             SMEM_GEMM);
    }

    const int n4 = MROWS * GK / 4;
    cvt_split<<<(n4 + 255) / 256, 256>>>(x, xh, xl, n4);
    xpose_qkv<<<(QKVC * GK + 255) / 256, 256>>>(Wq, Wk, Wv, wqh, wql);
    xpose_wo<<<(DIM * GK + 255) / 256, 256>>>(Wo, woh, wol);

    gemm_mma<<<dim3(QKVC / 128, MROWS / 128), 256, SMEM_GEMM>>>(
        xh, xl, wqh, wql, qkv, QKVC);

    attn_kernel<<<dim3(NH, BTN), 256,
                  (2 * SEQ * HD + SEQ) * sizeof(float)>>>(qw, kw);

    gemm_mma<<<dim3(DIM / 128, MROWS / 128), 256, SMEM_GEMM>>>(
        aah, aal, woh, wol, out, DIM);
}

// round 4
// speedup vs baseline: 2.9947x; 1.6332x over previous
#include <cuda_runtime.h>
#include <cuda_bf16.h>
#include <math.h>
#include <stdint.h>

// Problem constants
#define BTN   128
#define SEQ   256
#define DIM   1024
#define NH    16
#define NKV   4
#define GRP   4
#define HD    64
#define MROWS (BTN*SEQ)      // 32768
#define QKVC  1536
#define GK    1024
#define EPSV  1e-6f
#define SCALEV 0.125f
#define CAPV  50.0f

// ---------------------------------------------------------------------------
// Scratch (device globals)
// ---------------------------------------------------------------------------
__device__ float g_qkv[(size_t)MROWS * QKVC];
__device__ __align__(16) __nv_bfloat16 g_xh[(size_t)MROWS * GK];
__device__ __align__(16) __nv_bfloat16 g_xl[(size_t)MROWS * GK];
__device__ __align__(16) __nv_bfloat16 g_ah[(size_t)MROWS * GK];
__device__ __align__(16) __nv_bfloat16 g_al[(size_t)MROWS * GK];
__device__ __align__(16) __nv_bfloat16 g_wqkvh[(size_t)QKVC * GK]; // [n][k]
__device__ __align__(16) __nv_bfloat16 g_wqkvl[(size_t)QKVC * GK];
__device__ __align__(16) __nv_bfloat16 g_woh[(size_t)DIM * GK];
__device__ __align__(16) __nv_bfloat16 g_wol[(size_t)DIM * GK];

// ---------------------------------------------------------------------------
// helpers
// ---------------------------------------------------------------------------
__device__ __forceinline__ uint32_t smem_u32(const void* p) {
    uint32_t a;
    asm("{ .reg .u64 t; cvta.to.shared.u64 t, %1; cvt.u32.u64 %0, t; }"
        : "=r"(a) : "l"(p));
    return a;
}
__device__ __forceinline__ void cp16(uint32_t dst, const void* src) {
    asm volatile("cp.async.cg.shared.global [%0], [%1], 16;" :: "r"(dst), "l"(src));
}
__device__ __forceinline__ void ldmx4(uint32_t r[4], uint32_t addr) {
    asm volatile("ldmatrix.sync.aligned.m8n8.x4.shared.b16 {%0,%1,%2,%3}, [%4];"
                 : "=r"(r[0]), "=r"(r[1]), "=r"(r[2]), "=r"(r[3]) : "r"(addr));
}
__device__ __forceinline__ void ldmx4t(uint32_t r[4], uint32_t addr) {
    asm volatile("ldmatrix.sync.aligned.m8n8.x4.trans.shared.b16 {%0,%1,%2,%3}, [%4];"
                 : "=r"(r[0]), "=r"(r[1]), "=r"(r[2]), "=r"(r[3]) : "r"(addr));
}
__device__ __forceinline__ void mma16816(float c[4], const uint32_t a[4],
                                         const uint32_t b[2]) {
    asm volatile("mma.sync.aligned.m16n8k16.row.col.f32.bf16.bf16.f32 "
                 "{%0,%1,%2,%3}, {%4,%5,%6,%7}, {%8,%9}, {%0,%1,%2,%3};"
                 : "+f"(c[0]), "+f"(c[1]), "+f"(c[2]), "+f"(c[3])
                 : "r"(a[0]), "r"(a[1]), "r"(a[2]), "r"(a[3]),
                   "r"(b[0]), "r"(b[1]));
}
// split two floats into packed bf16 hi pair and lo (residual) pair
__device__ __forceinline__ void split2(float a, float b, uint32_t& H, uint32_t& L) {
    __nv_bfloat16 ah = __float2bfloat16(a), bh = __float2bfloat16(b);
    __nv_bfloat162 hh(ah, bh);
    H = *(uint32_t*)&hh;
    __nv_bfloat162 ll(__float2bfloat16(a - __bfloat162float(ah)),
                      __float2bfloat16(b - __bfloat162float(bh)));
    L = *(uint32_t*)&ll;
}
#define ASW(o) ((o) ^ (((o) >> 3) & 0x70))

// ---------------------------------------------------------------------------
// conversions
// ---------------------------------------------------------------------------
__global__ void cvt_split(const float* __restrict__ in,
                          __nv_bfloat16* __restrict__ h,
                          __nv_bfloat16* __restrict__ l, int n4)
{
    int i = blockIdx.x * blockDim.x + threadIdx.x;
    if (i >= n4) return;
    float4 v = ((const float4*)in)[i];
    uint32_t H0, L0, H1, L1;
    split2(v.x, v.y, H0, L0);
    split2(v.z, v.w, H1, L1);
    ((uint2*)h)[i] = make_uint2(H0, H1);
    ((uint2*)l)[i] = make_uint2(L0, L1);
}

__global__ void xpose_qkv(const float* __restrict__ Wq, const float* __restrict__ Wk,
                          const float* __restrict__ Wv,
                          __nv_bfloat16* __restrict__ th, __nv_bfloat16* __restrict__ tl)
{
    size_t idx = (size_t)blockIdx.x * blockDim.x + threadIdx.x;
    if (idx >= (size_t)QKVC * GK) return;
    int k = (int)(idx & (GK - 1));
    int n = (int)(idx >> 10);
    float v;
    if (n < DIM)            v = Wq[(size_t)k * (NH*HD)  + n];
    else if (n < DIM + 256) v = Wk[(size_t)k * (NKV*HD) + (n - DIM)];
    else                    v = Wv[(size_t)k * (NKV*HD) + (n - DIM - 256)];
    __nv_bfloat16 hv = __float2bfloat16(v);
    th[idx] = hv;
    tl[idx] = __float2bfloat16(v - __bfloat162float(hv));
}

__global__ void xpose_wo(const float* __restrict__ W,
                         __nv_bfloat16* __restrict__ th, __nv_bfloat16* __restrict__ tl)
{
    size_t idx = (size_t)blockIdx.x * blockDim.x + threadIdx.x;
    if (idx >= (size_t)DIM * GK) return;
    int k = (int)(idx & (GK - 1));
    int n = (int)(idx >> 10);
    float v = W[(size_t)k * DIM + n];
    __nv_bfloat16 hv = __float2bfloat16(v);
    th[idx] = hv;
    tl[idx] = __float2bfloat16(v - __bfloat162float(hv));
}

// ---------------------------------------------------------------------------
// HMMA bf16x3 GEMM: 128x128 CTA tile, BK=32, 2-stage cp.async, 2 CTAs/SM.
// ---------------------------------------------------------------------------
#define BK      32
#define NCHUNK  (GK / BK)
#define ROWB    80
#define TILE_B  (128 * ROWB)
#define STAGE_B (4 * TILE_B)
#define SMEM_GEMM (2 * STAGE_B + 1024)

__device__ __forceinline__ void g_load(uint32_t sbase, int tid,
    const __nv_bfloat16* a_h, const __nv_bfloat16* a_l,
    const __nv_bfloat16* b_h, const __nv_bfloat16* b_l, int koff)
{
    #pragma unroll
    for (int it = 0; it < 2; it++) {
        int idx = tid + it * 256;
        int row = idx >> 2;
        int c4  = idx & 3;
        uint32_t dst = sbase + row * ROWB + c4 * 16;
        size_t so = (size_t)row * GK + koff + c4 * 8;
        cp16(dst + 0 * TILE_B, a_h + so);
        cp16(dst + 1 * TILE_B, a_l + so);
        cp16(dst + 2 * TILE_B, b_h + so);
        cp16(dst + 3 * TILE_B, b_l + so);
    }
    asm volatile("cp.async.commit_group;" ::: "memory");
}

__global__ void __launch_bounds__(256, 2)
gemm_mma(const __nv_bfloat16* __restrict__ ah, const __nv_bfloat16* __restrict__ al,
         const __nv_bfloat16* __restrict__ bh, const __nv_bfloat16* __restrict__ bl,
         float* __restrict__ C, int ldc)
{
    extern __shared__ char smem_raw[];
    uint32_t sbr = smem_u32(smem_raw);
    const uint32_t sb = (sbr + 1023) & ~1023u;
    const int tid  = threadIdx.x;
    const int wid  = tid >> 5;
    const int lane = tid & 31;
    const int bm = blockIdx.y * 128;
    const int bn = blockIdx.x * 128;

    const __nv_bfloat16* Ah = ah + (size_t)bm * GK;
    const __nv_bfloat16* Al = al + (size_t)bm * GK;
    const __nv_bfloat16* Bh = bh + (size_t)bn * GK;
    const __nv_bfloat16* Bl = bl + (size_t)bn * GK;

    const int wm = (wid & 3) * 32;
    const int wn = (wid >> 2) * 64;
    const int ar = lane & 15;
    const int ac = (lane >> 4) * 16;

    float acc[2][8][4];
    #pragma unroll
    for (int i = 0; i < 2; i++)
        #pragma unroll
        for (int j = 0; j < 8; j++)
            #pragma unroll
            for (int e = 0; e < 4; e++) acc[i][j][e] = 0.f;

    g_load(sb,           tid, Ah, Al, Bh, Bl, 0);
    g_load(sb + STAGE_B, tid, Ah, Al, Bh, Bl, BK);

    for (int c = 0; c < NCHUNK; c++) {
        if (c + 1 < NCHUNK)
            asm volatile("cp.async.wait_group 1;" ::: "memory");
        else
            asm volatile("cp.async.wait_group 0;" ::: "memory");
        __syncthreads();

        const uint32_t st = sb + (c & 1) * STAGE_B;
        #pragma unroll
        for (int kk = 0; kk < 2; kk++) {
            const int kb = kk * 32;
            uint32_t fAh[2][4], fAl[2][4];
            #pragma unroll
            for (int mt = 0; mt < 2; mt++) {
                uint32_t arow = (uint32_t)(wm + mt * 16 + ar) * ROWB + kb + ac;
                ldmx4(fAh[mt], st + 0 * TILE_B + arow);
                ldmx4(fAl[mt], st + 1 * TILE_B + arow);
            }
            #pragma unroll
            for (int half = 0; half < 2; half++) {
                uint32_t fBh[4][2], fBl[4][2];
                #pragma unroll
                for (int np = 0; np < 2; np++) {
                    uint32_t brow = (uint32_t)(wn + (half * 2 + np) * 16
                                    + (lane & 7) + ((lane >> 4) & 1) * 8) * ROWB
                                    + kb + ((lane >> 3) & 1) * 16;
                    uint32_t t[4];
                    ldmx4(t, st + 2 * TILE_B + brow);
                    fBh[np*2][0] = t[0]; fBh[np*2][1] = t[1];
                    fBh[np*2+1][0] = t[2]; fBh[np*2+1][1] = t[3];
                    ldmx4(t, st + 3 * TILE_B + brow);
                    fBl[np*2][0] = t[0]; fBl[np*2][1] = t[1];
                    fBl[np*2+1][0] = t[2]; fBl[np*2+1][1] = t[3];
                }
                #pragma unroll
                for (int mt = 0; mt < 2; mt++)
                    #pragma unroll
                    for (int j = 0; j < 4; j++) {
                        const int nt = half * 4 + j;
                        mma16816(acc[mt][nt], fAh[mt], fBh[j]);
                        mma16816(acc[mt][nt], fAh[mt], fBl[j]);
                        mma16816(acc[mt][nt], fAl[mt], fBh[j]);
                    }
            }
        }
        __syncthreads();
        if (c + 2 < NCHUNK)
            g_load(st, tid, Ah, Al, Bh, Bl, (c + 2) * BK);
    }

    const int er = lane >> 2;
    const int ec = (lane & 3) * 2;
    #pragma unroll
    for (int mt = 0; mt < 2; mt++)
        #pragma unroll
        for (int nt = 0; nt < 8; nt++) {
            size_t row0 = (size_t)(bm + wm + mt * 16 + er) * ldc
                        + bn + wn + nt * 8 + ec;
            *(float2*)&C[row0]           = make_float2(acc[mt][nt][0], acc[mt][nt][1]);
            *(float2*)&C[row0 + 8 * ldc] = make_float2(acc[mt][nt][2], acc[mt][nt][3]);
        }
}

// ---------------------------------------------------------------------------
// Tensor-core attention: block per (bt, h), 256 threads (8 warps).
// Stage Q/K/V as bf16 hi/lo in smem (rmsnorm + scales folded).
// Warp w: queries [32w, 32w+32). Key blocks of 64.
// 3-term bf16x3 for QK (logits) and PV.
// p = exp(l - CAP) = exp(-2*CAP/(u+1)), u = exp(2z/CAP); fixed max.
// ---------------------------------------------------------------------------
#define ATT_SMEM (6 * 32768 + 1024)

__global__ void __launch_bounds__(256, 1)
attn_mma(const float* __restrict__ qw, const float* __restrict__ kw)
{
    extern __shared__ char smem_raw[];
    uint32_t sbr = smem_u32(smem_raw);
    const uint32_t sb = (sbr + 1023) & ~1023u;
    char* smb = smem_raw + (sb - sbr);
    const uint32_t sQh = sb, sQl = sb + 32768, sKh = sb + 65536,
                   sKl = sb + 98304, sVh = sb + 131072, sVl = sb + 163840;

    const int h  = blockIdx.x;
    const int bt = blockIdx.y;
    const int kvh = h >> 2;
    const int tid = threadIdx.x;
    const int lane = tid & 31;
    const int wid = tid >> 5;

    const float* base = g_qkv + (size_t)bt * SEQ * QKVC;

    // ---- staging: thread r handles row r of Q, K, V ----
    {
        const int r = tid;
        const float* qp = base + (size_t)r * QKVC + h * HD;
        const float* kp = base + (size_t)r * QKVC + DIM + kvh * HD;
        const float* vp = base + (size_t)r * QKVC + DIM + NKV * HD + kvh * HD;
        float qv[HD], kv[HD], vv[HD];
        float sq = 0.f, sk = 0.f;
        #pragma unroll
        for (int d = 0; d < HD; d += 4) {
            float4 a = *(const float4*)(qp + d);
            qv[d] = a.x; qv[d+1] = a.y; qv[d+2] = a.z; qv[d+3] = a.w;
            sq += a.x*a.x + a.y*a.y + a.z*a.z + a.w*a.w;
            float4 b = *(const float4*)(kp + d);
            kv[d] = b.x; kv[d+1] = b.y; kv[d+2] = b.z; kv[d+3] = b.w;
            sk += b.x*b.x + b.y*b.y + b.z*b.z + b.w*b.w;
            float4 c = *(const float4*)(vp + d);
            vv[d] = c.x; vv[d+1] = c.y; vv[d+2] = c.z; vv[d+3] = c.w;
        }
        const float rq = rsqrtf(sq * (1.0f / HD) + EPSV);
        const float rk = rsqrtf(sk * (1.0f / HD) + EPSV);
        const float qf = rq * SCALEV * (2.0f / CAPV);
        #pragma unroll
        for (int d = 0; d < HD; d++) {
            qv[d] *= qf * __ldg(&qw[d]) * __ldg(&kw[d]);
            kv[d] *= rk;
        }
        #pragma unroll
        for (int d0 = 0; d0 < HD; d0 += 8) {
            uint32_t off = ASW((uint32_t)(r * 128 + d0 * 2));
            uint4 H, L;
            split2(qv[d0+0], qv[d0+1], H.x, L.x);
            split2(qv[d0+2], qv[d0+3], H.y, L.y);
            split2(qv[d0+4], qv[d0+5], H.z, L.z);
            split2(qv[d0+6], qv[d0+7], H.w, L.w);
            *(uint4*)(smb + (sQh - sb) + off) = H;
            *(uint4*)(smb + (sQl - sb) + off) = L;
            split2(kv[d0+0], kv[d0+1], H.x, L.x);
            split2(kv[d0+2], kv[d0+3], H.y, L.y);
            split2(kv[d0+4], kv[d0+5], H.z, L.z);
            split2(kv[d0+6], kv[d0+7], H.w, L.w);
            *(uint4*)(smb + (sKh - sb) + off) = H;
            *(uint4*)(smb + (sKl - sb) + off) = L;
            split2(vv[d0+0], vv[d0+1], H.x, L.x);
            split2(vv[d0+2], vv[d0+3], H.y, L.y);
            split2(vv[d0+4], vv[d0+5], H.z, L.z);
            split2(vv[d0+6], vv[d0+7], H.w, L.w);
            *(uint4*)(smb + (sVh - sb) + off) = H;
            *(uint4*)(smb + (sVl - sb) + off) = L;
        }
    }
    __syncthreads();

    const int qm = wid * 32;
    float acc[2][8][4];
    float rsum[2][2];
    #pragma unroll
    for (int i = 0; i < 2; i++) {
        rsum[i][0] = rsum[i][1] = 0.f;
        #pragma unroll
        for (int j = 0; j < 8; j++)
            #pragma unroll
            for (int e = 0; e < 4; e++) acc[i][j][e] = 0.f;
    }

    for (int kb = 0; kb < 4; kb++) {
        // ---- QK^T: S = Qhat @ Khat^T (2z/CAP directly) ----
        float S[2][8][4];
        #pragma unroll
        for (int i = 0; i < 2; i++)
            #pragma unroll
            for (int j = 0; j < 8; j++)
                #pragma unroll
                for (int e = 0; e < 4; e++) S[i][j][e] = 0.f;

        #pragma unroll
        for (int ks = 0; ks < 4; ks++) {
            uint32_t fQh[2][4], fQl[2][4];
            #pragma unroll
            for (int mt = 0; mt < 2; mt++) {
                uint32_t off = ASW((uint32_t)((qm + mt*16 + (lane & 15)) * 128
                              + ks * 32 + ((lane >> 4) & 1) * 16));
                ldmx4(fQh[mt], sQh + off);
                ldmx4(fQl[mt], sQl + off);
            }
            uint32_t fKh[8][2], fKl[8][2];
            #pragma unroll
            for (int np = 0; np < 4; np++) {
                uint32_t krow = kb*64 + np*16 + (lane & 7) + ((lane >> 4) & 1) * 8;
                uint32_t off = ASW(krow * 128 + ks * 32 + ((lane >> 3) & 1) * 16);
                uint32_t t[4];
                ldmx4(t, sKh + off);
                fKh[2*np][0] = t[0]; fKh[2*np][1] = t[1];
                fKh[2*np+1][0] = t[2]; fKh[2*np+1][1] = t[3];
                ldmx4(t, sKl + off);
                fKl[2*np][0] = t[0]; fKl[2*np][1] = t[1];
                fKl[2*np+1][0] = t[2]; fKl[2*np+1][1] = t[3];
            }
            #pragma unroll
            for (int mt = 0; mt < 2; mt++)
                #pragma unroll
                for (int nt = 0; nt < 8; nt++) {
                    mma16816(S[mt][nt], fQh[mt], fKh[nt]);
                    mma16816(S[mt][nt], fQh[mt], fKl[nt]);
                    mma16816(S[mt][nt], fQl[mt], fKh[nt]);
                }
        }

        // ---- softmax numerator + pack P fragments ----
        uint32_t pAh[2][4][4], pAl[2][4][4];
        #pragma unroll
        for (int mt = 0; mt < 2; mt++) {
            #pragma unroll
            for (int nt = 0; nt < 8; nt++) {
                #pragma unroll
                for (int e = 0; e < 4; e++) {
                    float u = __expf(S[mt][nt][e]);
                    S[mt][nt][e] = __expf(__fdividef(-2.0f * CAPV, u + 1.0f));
                }
                rsum[mt][0] += S[mt][nt][0] + S[mt][nt][1];
                rsum[mt][1] += S[mt][nt][2] + S[mt][nt][3];
            }
            #pragma unroll
            for (int kk = 0; kk < 4; kk++) {
                split2(S[mt][2*kk][0],   S[mt][2*kk][1],   pAh[mt][kk][0], pAl[mt][kk][0]);
                split2(S[mt][2*kk][2],   S[mt][2*kk][3],   pAh[mt][kk][1], pAl[mt][kk][1]);
                split2(S[mt][2*kk+1][0], S[mt][2*kk+1][1], pAh[mt][kk][2], pAl[mt][kk][2]);
                split2(S[mt][2*kk+1][2], S[mt][2*kk+1][3], pAh[mt][kk][3], pAl[mt][kk][3]);
            }
        }

        // ---- P @ V ----
        #pragma unroll
        for (int kk = 0; kk < 4; kk++) {
            uint32_t fVh[8][2], fVl[8][2];
            #pragma unroll
            for (int np = 0; np < 4; np++) {
                uint32_t vrow = kb*64 + kk*16 + (lane & 7) + ((lane >> 3) & 1) * 8;
                uint32_t off = ASW(vrow * 128 + (np*16 + ((lane >> 4) & 1) * 8) * 2);
                uint32_t t[4];
                ldmx4t(t, sVh + off);
                fVh[2*np][0] = t[0]; fVh[2*np][1] = t[1];
                fVh[2*np+1][0] = t[2]; fVh[2*np+1][1] = t[3];
                ldmx4t(t, sVl + off);
                fVl[2*np][0] = t[0]; fVl[2*np][1] = t[1];
                fVl[2*np+1][0] = t[2]; fVl[2*np+1][1] = t[3];
            }
            #pragma unroll
            for (int mt = 0; mt < 2; mt++)
                #pragma unroll
                for (int nt = 0; nt < 8; nt++) {
                    mma16816(acc[mt][nt], pAh[mt][kk], fVh[nt]);
                    mma16816(acc[mt][nt], pAh[mt][kk], fVl[nt]);
                    mma16816(acc[mt][nt], pAl[mt][kk], fVh[nt]);
                }
        }
    }

    // ---- normalize + write bf16 hi/lo ----
    #pragma unroll
    for (int mt = 0; mt < 2; mt++) {
        rsum[mt][0] += __shfl_xor_sync(0xffffffffu, rsum[mt][0], 1);
        rsum[mt][0] += __shfl_xor_sync(0xffffffffu, rsum[mt][0], 2);
        rsum[mt][1] += __shfl_xor_sync(0xffffffffu, rsum[mt][1], 1);
        rsum[mt][1] += __shfl_xor_sync(0xffffffffu, rsum[mt][1], 2);
    }
    #pragma unroll
    for (int mt = 0; mt < 2; mt++) {
        const float inv0 = 1.0f / rsum[mt][0];
        const float inv1 = 1.0f / rsum[mt][1];
        #pragma unroll
        for (int nt = 0; nt < 8; nt++) {
            int rq_ = qm + mt*16 + (lane >> 2);
            int col = nt*8 + (lane & 3) * 2;
            size_t o0 = (size_t)(bt * SEQ + rq_) * GK + h * HD + col;
            size_t o1 = o0 + (size_t)8 * GK;
            uint32_t H, L;
            split2(acc[mt][nt][0] * inv0, acc[mt][nt][1] * inv0, H, L);
            *(uint32_t*)(g_ah + o0) = H;
            *(uint32_t*)(g_al + o0) = L;
            split2(acc[mt][nt][2] * inv1, acc[mt][nt][3] * inv1, H, L);
            *(uint32_t*)(g_ah + o1) = H;
            *(uint32_t*)(g_al + o1) = L;
        }
    }
}

// ---------------------------------------------------------------------------
// launch
// ---------------------------------------------------------------------------
extern "C" void kernel_launch(void* const* d_in, const int* in_sizes, int n_in,
                              void* d_out, int out_size)
{
    const float* x  = (const float*)d_in[0];
    const float* Wq = (const float*)d_in[1];
    const float* Wk = (const float*)d_in[2];
    const float* Wv = (const float*)d_in[3];
    const float* Wo = (const float*)d_in[4];
    const float* qw = (const float*)d_in[5];
    const float* kw = (const float*)d_in[6];
    float* out = (float*)d_out;

    static float* qkv = nullptr;
    static __nv_bfloat16 *xh, *xl, *aah, *aal, *wqh, *wql, *woh, *wol;
    if (!qkv) {
        cudaGetSymbolAddress((void**)&qkv, g_qkv);
        cudaGetSymbolAddress((void**)&xh,  g_xh);
        cudaGetSymbolAddress((void**)&xl,  g_xl);
        cudaGetSymbolAddress((void**)&aah, g_ah);
        cudaGetSymbolAddress((void**)&aal, g_al);
        cudaGetSymbolAddress((void**)&wqh, g_wqkvh);
        cudaGetSymbolAddress((void**)&wql, g_wqkvl);
        cudaGetSymbolAddress((void**)&woh, g_woh);
        cudaGetSymbolAddress((void**)&wol, g_wol);
        cudaFuncSetAttribute(attn_mma,
                             cudaFuncAttributeMaxDynamicSharedMemorySize, ATT_SMEM);
        cudaFuncSetAttribute(gemm_mma,
                             cudaFuncAttributeMaxDynamicSharedMemorySize, SMEM_GEMM);
    }

    const int n4 = MROWS * GK / 4;
    cvt_split<<<(n4 + 255) / 256, 256>>>(x, xh, xl, n4);
    xpose_qkv<<<(QKVC * GK + 255) / 256, 256>>>(Wq, Wk, Wv, wqh, wql);
    xpose_wo<<<(DIM * GK + 255) / 256, 256>>>(Wo, woh, wol);

    gemm_mma<<<dim3(QKVC / 128, MROWS / 128), 256, SMEM_GEMM>>>(
        xh, xl, wqh, wql, qkv, QKVC);

    attn_mma<<<dim3(NH, BTN), 256, ATT_SMEM>>>(qw, kw);

    gemm_mma<<<dim3(DIM / 128, MROWS / 128), 256, SMEM_GEMM>>>(
        aah, aal, woh, wol, out, DIM);
}